// round 1
// baseline (speedup 1.0000x reference)
#include <cuda_runtime.h>

#define BB 8
#define CC 512
#define TT 8192
#define OPT 8              // outputs per thread
#define NT 256             // threads per block
#define CHUNK (NT * OPT)   // 2048 outputs per block
#define NCHUNK (TT / CHUNK) // 4 blocks per (b,c) row
#define NZ (2 * OPT + 10)  // 26 snake values per thread

__global__ __launch_bounds__(NT) void aa_fused_kernel(
    const float* __restrict__ x,
    const float* __restrict__ alpha,
    const float* __restrict__ beta,
    const float* __restrict__ fu,
    const float* __restrict__ fd,
    float* __restrict__ out)
{
    __shared__ float s_g0[6], s_g1[6], s_fd[12];
    __shared__ float s_a, s_ib;

    const int tid = threadIdx.x;
    const int bid = blockIdx.x;
    const int row = bid >> 2;      // NCHUNK == 4
    const int chunk = bid & 3;
    const int c = row & (CC - 1);

    // Stage filters (with the 2x upsample gain folded in) + per-channel snake params.
    if (tid < 6)        s_g0[tid] = 2.0f * fu[10 - 2 * tid];        // odd-n phase taps
    else if (tid < 12)  { int r = tid - 6; s_g1[r] = 2.0f * fu[11 - 2 * r]; } // even-n phase
    else if (tid < 24)  s_fd[tid - 12] = fd[tid - 12];
    else if (tid == 24) s_a  = expf(alpha[c]);
    else if (tid == 25) s_ib = 1.0f / (expf(beta[c]) + 1e-9f);
    __syncthreads();

    float g0[6], g1[6], fdr[12];
    #pragma unroll
    for (int r = 0; r < 6; r++) { g0[r] = s_g0[r]; g1[r] = s_g1[r]; }
    #pragma unroll
    for (int q = 0; q < 12; q++) fdr[q] = s_fd[q];
    const float a  = s_a;
    const float ib = s_ib;

    const float* xrow = x + (size_t)row * TT;
    float* orow = out + (size_t)row * TT;
    const int tb = chunk * CHUNK + tid * OPT;

    float z[NZ];

    const bool edge = (tb == 0) || (tb == TT - OPT);
    if (!edge) {
        // Fast path: register-resident x window x[tb-8 .. tb+15], aligned float4 loads.
        float xw[24];
        const float4* xv = (const float4*)(xrow + tb - 8);
        #pragma unroll
        for (int i = 0; i < 6; i++) {
            float4 v = xv[i];
            xw[4 * i + 0] = v.x; xw[4 * i + 1] = v.y;
            xw[4 * i + 2] = v.z; xw[4 * i + 3] = v.w;
        }
        // z[s] corresponds to upsampled index n = 2*tb - 5 + s.
        // s even -> n odd  -> taps g0, x base m-2 = tb-5+s/2     -> xw[3 + s/2 + r]
        // s odd  -> n even -> taps g1, x base m-3 = tb-5+(s-1)/2 -> xw[3 + (s>>1) + r]
        #pragma unroll
        for (int s = 0; s < NZ; s++) {
            const int h = 3 + (s >> 1);
            float acc;
            if ((s & 1) == 0) {
                acc = g0[0] * xw[h];
                #pragma unroll
                for (int r = 1; r < 6; r++) acc += g0[r] * xw[h + r];
            } else {
                acc = g1[0] * xw[h];
                #pragma unroll
                for (int r = 1; r < 6; r++) acc += g1[r] * xw[h + r];
            }
            const float sv = __sinf(acc * a);
            z[s] = acc + sv * sv * ib;
        }
    } else {
        // Edge path (first/last 8-output chunk of each row): clamped indices, global loads.
        #pragma unroll
        for (int s = 0; s < NZ; s++) {
            int n = 2 * tb - 5 + s;
            n = min(max(n, 0), 2 * TT - 1);
            const int m = n >> 1;
            float acc = 0.0f;
            if (n & 1) {
                #pragma unroll
                for (int r = 0; r < 6; r++) {
                    const int j = min(max(m - 2 + r, 0), TT - 1);
                    acc += g0[r] * __ldg(&xrow[j]);
                }
            } else {
                #pragma unroll
                for (int r = 0; r < 6; r++) {
                    const int j = min(max(m - 3 + r, 0), TT - 1);
                    acc += g1[r] * __ldg(&xrow[j]);
                }
            }
            const float sv = __sinf(acc * a);
            z[s] = acc + sv * sv * ib;
        }
    }

    // Downsample: out[tb+i] = sum_q fd[q] * z[2i + q]
    float o[OPT];
    #pragma unroll
    for (int i = 0; i < OPT; i++) {
        float acc = fdr[0] * z[2 * i];
        #pragma unroll
        for (int q = 1; q < 12; q++) acc += fdr[q] * z[2 * i + q];
        o[i] = acc;
    }
    float4* ov = (float4*)(orow + tb);
    ov[0] = make_float4(o[0], o[1], o[2], o[3]);
    ov[1] = make_float4(o[4], o[5], o[6], o[7]);
}

extern "C" void kernel_launch(void* const* d_in, const int* in_sizes, int n_in,
                              void* d_out, int out_size)
{
    const float* x     = (const float*)d_in[0];
    const float* alpha = (const float*)d_in[1];
    const float* beta  = (const float*)d_in[2];
    const float* fu    = (const float*)d_in[3];
    const float* fd    = (const float*)d_in[4];
    float* out = (float*)d_out;

    const int grid = BB * CC * NCHUNK; // 16384
    aa_fused_kernel<<<grid, NT>>>(x, alpha, beta, fu, fd, out);
}

// round 2
// speedup vs baseline: 1.0783x; 1.0783x over previous
#include <cuda_runtime.h>

#define BB 8
#define CC 512
#define TT 8192
#define OPT 8              // outputs per thread
#define NT 256             // threads per block
#define CHUNK (NT * OPT)   // 2048 outputs per block
#define NCHUNK (TT / CHUNK) // 4 blocks per (b,c) row
#define NZ (2 * OPT + 10)  // 26 snake values per thread -> 13 packed pairs

typedef unsigned long long u64;

__device__ __forceinline__ u64 pk2(float lo, float hi) {
    u64 r; asm("mov.b64 %0, {%1, %2};" : "=l"(r) : "f"(lo), "f"(hi)); return r;
}
__device__ __forceinline__ void upk2(u64 v, float& lo, float& hi) {
    asm("mov.b64 {%0, %1}, %2;" : "=f"(lo), "=f"(hi) : "l"(v));
}
__device__ __forceinline__ u64 fma2(u64 a, u64 b, u64 c) {
    u64 d; asm("fma.rn.f32x2 %0, %1, %2, %3;" : "=l"(d) : "l"(a), "l"(b), "l"(c)); return d;
}
__device__ __forceinline__ u64 mul2(u64 a, u64 b) {
    u64 d; asm("mul.rn.f32x2 %0, %1, %2;" : "=l"(d) : "l"(a), "l"(b)); return d;
}

__global__ __launch_bounds__(NT) void aa_fused_kernel(
    const float* __restrict__ x,
    const float* __restrict__ alpha,
    const float* __restrict__ beta,
    const float* __restrict__ fu,
    const float* __restrict__ fd,
    float* __restrict__ out)
{
    __shared__ float s_g0[6], s_g1[6], s_fd[12];
    __shared__ float s_a, s_ib;

    const int tid = threadIdx.x;
    const int bid = blockIdx.x;
    const int row = bid >> 2;      // NCHUNK == 4
    const int chunk = bid & 3;
    const int c = row & (CC - 1);

    // Stage filters (2x upsample gain folded in) + per-channel snake params.
    if (tid < 6)        s_g0[tid] = 2.0f * fu[10 - 2 * tid];                   // even-pair lane (odd n)
    else if (tid < 12)  { int r = tid - 6; s_g1[r] = 2.0f * fu[11 - 2 * r]; }  // odd-pair lane (even n)
    else if (tid < 24)  s_fd[tid - 12] = fd[tid - 12];
    else if (tid == 24) s_a  = expf(alpha[c]);
    else if (tid == 25) s_ib = 1.0f / (expf(beta[c]) + 1e-9f);
    __syncthreads();

    // Packed up-filter taps: lane0 = g0[r] (z even-s), lane1 = g1[r] (z odd-s)
    u64 g2[6];
    #pragma unroll
    for (int r = 0; r < 6; r++) g2[r] = pk2(s_g0[r], s_g1[r]);
    const float a  = s_a;
    const float ib = s_ib;
    const u64 a2  = pk2(a, a);
    const u64 ib2 = pk2(ib, ib);

    const float* xrow = x + (size_t)row * TT;
    float* orow = out + (size_t)row * TT;
    const int tb = chunk * CHUNK + tid * OPT;

    u64 zp[NZ / 2];  // zp[p] = (z[2p], z[2p+1]); z[s] is upsampled index n = 2*tb - 5 + s

    const bool edge = (tb == 0) || (tb == TT - OPT);
    if (!edge) {
        // Fast path: register-resident window x[tb-8 .. tb+15], aligned float4 loads.
        float xw[24];
        const float4* xv = (const float4*)(xrow + tb - 8);
        #pragma unroll
        for (int i = 0; i < 6; i++) {
            float4 v = xv[i];
            xw[4 * i + 0] = v.x; xw[4 * i + 1] = v.y;
            xw[4 * i + 2] = v.z; xw[4 * i + 3] = v.w;
        }
        // Pair (z[2p], z[2p+1]) shares window xw[3+p .. 3+p+5]:
        //   z[2p]   (n odd)  = sum_r g0[r]*xw[3+p+r]
        //   z[2p+1] (n even) = sum_r g1[r]*xw[3+p+r]
        #pragma unroll
        for (int p = 0; p < NZ / 2; p++) {
            u64 acc = mul2(g2[0], pk2(xw[3 + p], xw[3 + p]));
            #pragma unroll
            for (int r = 1; r < 6; r++)
                acc = fma2(g2[r], pk2(xw[3 + p + r], xw[3 + p + r]), acc);
            // snake (lane-wise)
            float t0, t1; upk2(mul2(acc, a2), t0, t1);
            u64 s2 = pk2(__sinf(t0), __sinf(t1));
            zp[p] = fma2(mul2(s2, s2), ib2, acc);
        }
    } else {
        // Edge path (first/last chunk of each row): clamped indices, scalar.
        #pragma unroll
        for (int p = 0; p < NZ / 2; p++) {
            float zz[2];
            #pragma unroll
            for (int l = 0; l < 2; l++) {
                int n = 2 * tb - 5 + 2 * p + l;
                n = min(max(n, 0), 2 * TT - 1);
                const int m = n >> 1;
                float acc = 0.0f;
                if (n & 1) {
                    #pragma unroll
                    for (int r = 0; r < 6; r++) {
                        const int j = min(max(m - 2 + r, 0), TT - 1);
                        acc += s_g0[r] * __ldg(&xrow[j]);
                    }
                } else {
                    #pragma unroll
                    for (int r = 0; r < 6; r++) {
                        const int j = min(max(m - 3 + r, 0), TT - 1);
                        acc += s_g1[r] * __ldg(&xrow[j]);
                    }
                }
                const float sv = __sinf(acc * a);
                zz[l] = acc + sv * sv * ib;
            }
            zp[p] = pk2(zz[0], zz[1]);
        }
    }

    // Packed down-filter taps loaded late to reduce register overlap with the up stage.
    u64 fd2[6];
    #pragma unroll
    for (int u = 0; u < 6; u++) fd2[u] = pk2(s_fd[2 * u], s_fd[2 * u + 1]);

    // Downsample: out[i] = sum_u fd[2u]*z[2i+2u] + fd[2u+1]*z[2i+2u+1]
    //                    = hadd( sum_u fd2[u] .* zp[i+u] )
    float o[OPT];
    #pragma unroll
    for (int i = 0; i < OPT; i++) {
        u64 acc = mul2(fd2[0], zp[i]);
        #pragma unroll
        for (int u = 1; u < 6; u++) acc = fma2(fd2[u], zp[i + u], acc);
        float lo, hi; upk2(acc, lo, hi);
        o[i] = lo + hi;
    }
    float4* ov = (float4*)(orow + tb);
    ov[0] = make_float4(o[0], o[1], o[2], o[3]);
    ov[1] = make_float4(o[4], o[5], o[6], o[7]);
}

extern "C" void kernel_launch(void* const* d_in, const int* in_sizes, int n_in,
                              void* d_out, int out_size)
{
    const float* x     = (const float*)d_in[0];
    const float* alpha = (const float*)d_in[1];
    const float* beta  = (const float*)d_in[2];
    const float* fu    = (const float*)d_in[3];
    const float* fd    = (const float*)d_in[4];
    float* out = (float*)d_out;

    const int grid = BB * CC * NCHUNK; // 16384
    aa_fused_kernel<<<grid, NT>>>(x, alpha, beta, fu, fd, out);
}